// round 13
// baseline (speedup 1.0000x reference)
#include <cuda_runtime.h>
#include <cuda_bf16.h>
#include <math.h>

#define DDIM 128
#define NMAX 50000
#define EMAX 800000
#define ASTR 36            // per-chunk bf16x2 stride (32 data + 4 pad), %32==4 -> conflict-free
#define AFSTR 68           // full-K bf16x2 stride (64 data + 4 pad), %32==4 -> conflict-free
#define KC   64            // k-chunk (32 bf16x2)
#define CAP  64            // ELL capacity per node (Poisson(16): max deg ~45)
#define OVFMAX 65536
#define K2   (DDIM / 2)    // 64 bf16x2 per row
#define K4   (DDIM / 4)    // 32 uint4 per packed row

// Scratch (alloc-free rule: __device__ globals; zero-initialized at load).
// State protocol across launches: g_deg self-cleaned by gather, g_ovf_cnt
// reset by dual_kernel, everything else fully rewritten each launch.
__device__ uint4    g_agg[(size_t)NMAX * K4];    // packed bf16-split aggx {h0,h1,l0,l1}
__device__ float    g_rowsum[NMAX];              // sum of vals per dst node
__device__ int      g_deg[NMAX];
__device__ uint2    g_ell[(size_t)NMAX * CAP];   // (src, val_bits) per slot
__device__ int      g_ovf_cnt;
__device__ uint4    g_ovf[OVFMAX];               // (src, dst, val_bits, -)
// pre-split weights, bf16x2 hi/lo, layout [n][k2]
__device__ unsigned gW0h[DDIM * K2], gW0l[DDIM * K2];
__device__ unsigned gW1h[DDIM * K2], gW1l[DDIM * K2];

// ---------------------------------------------------------------------------
__device__ __forceinline__ void split_pair(float x, float y, unsigned& hp, unsigned& lp) {
    __nv_bfloat16 hx = __float2bfloat16_rn(x);
    __nv_bfloat16 hy = __float2bfloat16_rn(y);
    __nv_bfloat16 lx = __float2bfloat16_rn(x - __bfloat162float(hx));
    __nv_bfloat16 ly = __float2bfloat16_rn(y - __bfloat162float(hy));
    hp = (unsigned)__bfloat16_as_ushort(hx) | ((unsigned)__bfloat16_as_ushort(hy) << 16);
    lp = (unsigned)__bfloat16_as_ushort(lx) | ((unsigned)__bfloat16_as_ushort(ly) << 16);
}

__device__ __forceinline__ void mma_bf16(float c[4], const unsigned a[4],
                                         unsigned b0, unsigned b1) {
    asm volatile(
        "mma.sync.aligned.m16n8k16.row.col.f32.bf16.bf16.f32 "
        "{%0,%1,%2,%3}, {%4,%5,%6,%7}, {%8,%9}, {%0,%1,%2,%3};"
        : "+f"(c[0]), "+f"(c[1]), "+f"(c[2]), "+f"(c[3])
        : "r"(a[0]), "r"(a[1]), "r"(a[2]), "r"(a[3]), "r"(b0), "r"(b1));
}

__device__ __forceinline__ void fma4(float4& a, float4 s, float v) {
    a.x = fmaf(s.x, v, a.x); a.y = fmaf(s.y, v, a.y);
    a.z = fmaf(s.z, v, a.z); a.w = fmaf(s.w, v, a.w);
}

// ---------------------------------------------------------------------------
// Kernel 1: ELL fill chunks || weight pre-split, one grid (independent work;
// g_deg arrives zeroed via the cross-launch protocol).
// ---------------------------------------------------------------------------
__global__ void fillw_kernel(const int* __restrict__ src,
                             const int* __restrict__ dst,
                             const float* __restrict__ vals,
                             const float* __restrict__ W_gc,
                             const float* __restrict__ W2,
                             int e, int fillchunks) {
    int b = blockIdx.x;
    if (b < fillchunks) {
        int base = b * 1024 + threadIdx.x * 4;
#pragma unroll
        for (int j = 0; j < 4; j++) {
            int i = base + j;
            if (i >= e) break;
            int d = __ldg(dst + i);
            int s = __ldg(src + i);
            float v = __ldg(vals + i);
            int slot = atomicAdd(&g_deg[d], 1);
            if (slot < CAP) {
                g_ell[(size_t)d * CAP + slot] = make_uint2((unsigned)s, __float_as_uint(v));
            } else {
                int o = atomicAdd(&g_ovf_cnt, 1);
                if (o < OVFMAX)
                    g_ovf[o] = make_uint4((unsigned)s, (unsigned)d, __float_as_uint(v), 0u);
            }
        }
        return;
    }
    int i = (b - fillchunks) * 256 + threadIdx.x;      // [0, 32768)
    if (i < DDIM * K2) {                               // W_gc: [k][n] -> [n][k2]
        int nn = i & (DDIM - 1), k2 = i >> 7;
        float w0 = __ldg(W_gc + (size_t)(2 * k2) * DDIM + nn);
        float w1 = __ldg(W_gc + (size_t)(2 * k2 + 1) * DDIM + nn);
        unsigned hp, lp;
        split_pair(w0, w1, hp, lp);
        gW0h[nn * K2 + k2] = hp;
        gW0l[nn * K2 + k2] = lp;
    } else if (i < 2 * DDIM * K2) {                    // W2: [n][k] -> [n][k2]
        int j = i - DDIM * K2;
        int nn = j >> 6, k2 = j & 63;
        float w0 = __ldg(W2 + (size_t)nn * DDIM + 2 * k2);
        float w1 = __ldg(W2 + (size_t)nn * DDIM + 2 * k2 + 1);
        unsigned hp, lp;
        split_pair(w0, w1, hp, lp);
        gW1h[nn * K2 + k2] = hp;
        gW1l[nn * K2 + k2] = lp;
    }
}

// ---------------------------------------------------------------------------
// Kernel 2: gather on x (associativity: aggx = Adj @ x, rowsum = Adj @ 1).
// One warp per node, 8 edges in flight. Emits packed bf16-split aggx
// (no ReLU here — it comes after GEMM0). Self-cleans g_deg for next launch.
// ---------------------------------------------------------------------------
__global__ void __launch_bounds__(256)
gather_kernel(const float* __restrict__ x, int n) {
    int g = blockIdx.x * blockDim.x + threadIdx.x;
    int node = g >> 5;
    int lane = g & 31;
    if (node >= n) return;

    int raw = __ldg(&g_deg[node]);
    int cnt = min(raw, CAP);
    const uint4* el4 = (const uint4*)(g_ell + (size_t)node * CAP);

    float4 acc = make_float4(0.f, 0.f, 0.f, 0.f);
    float vsum = 0.f;
    int nb8 = cnt >> 3;

    for (int q = 0; q < nb8; q++) {
        const uint4* p = el4 + 4 * q;
        uint4 m0 = __ldg(p),     m1 = __ldg(p + 1);
        uint4 m2 = __ldg(p + 2), m3 = __ldg(p + 3);
        float4 s0 = ((const float4*)(x + (size_t)m0.x * DDIM))[lane];
        float4 s1 = ((const float4*)(x + (size_t)m0.z * DDIM))[lane];
        float4 s2 = ((const float4*)(x + (size_t)m1.x * DDIM))[lane];
        float4 s3 = ((const float4*)(x + (size_t)m1.z * DDIM))[lane];
        float4 s4 = ((const float4*)(x + (size_t)m2.x * DDIM))[lane];
        float4 s5 = ((const float4*)(x + (size_t)m2.z * DDIM))[lane];
        float4 s6 = ((const float4*)(x + (size_t)m3.x * DDIM))[lane];
        float4 s7 = ((const float4*)(x + (size_t)m3.z * DDIM))[lane];
        float v0 = __uint_as_float(m0.y), v1 = __uint_as_float(m0.w);
        float v2 = __uint_as_float(m1.y), v3 = __uint_as_float(m1.w);
        float v4 = __uint_as_float(m2.y), v5 = __uint_as_float(m2.w);
        float v6 = __uint_as_float(m3.y), v7 = __uint_as_float(m3.w);
        fma4(acc, s0, v0); fma4(acc, s1, v1);
        fma4(acc, s2, v2); fma4(acc, s3, v3);
        fma4(acc, s4, v4); fma4(acc, s5, v5);
        fma4(acc, s6, v6); fma4(acc, s7, v7);
        vsum += v0 + v1 + v2 + v3 + v4 + v5 + v6 + v7;
    }
    int i = nb8 * 8;
    if (i + 3 < cnt) {
        const uint4* p = el4 + (i >> 1);
        uint4 m0 = __ldg(p), m1 = __ldg(p + 1);
        float4 s0 = ((const float4*)(x + (size_t)m0.x * DDIM))[lane];
        float4 s1 = ((const float4*)(x + (size_t)m0.z * DDIM))[lane];
        float4 s2 = ((const float4*)(x + (size_t)m1.x * DDIM))[lane];
        float4 s3 = ((const float4*)(x + (size_t)m1.z * DDIM))[lane];
        float v0 = __uint_as_float(m0.y), v1 = __uint_as_float(m0.w);
        float v2 = __uint_as_float(m1.y), v3 = __uint_as_float(m1.w);
        fma4(acc, s0, v0); fma4(acc, s1, v1);
        fma4(acc, s2, v2); fma4(acc, s3, v3);
        vsum += v0 + v1 + v2 + v3;
        i += 4;
    }
    for (; i < cnt; i++) {
        uint2 m = __ldg(g_ell + (size_t)node * CAP + i);
        float v = __uint_as_float(m.y);
        float4 s = ((const float4*)(x + (size_t)m.x * DDIM))[lane];
        fma4(acc, s, v);
        vsum += v;
    }
    if (raw > CAP) {        // ~never: this node's overflow edges
        int c = min(g_ovf_cnt, OVFMAX);
        for (int j = 0; j < c; j++) {
            uint4 m = g_ovf[j];
            if (m.y == (unsigned)node) {
                float v = __uint_as_float(m.z);
                float4 s = ((const float4*)(x + (size_t)m.x * DDIM))[lane];
                fma4(acc, s, v);
                vsum += v;
            }
        }
    }

    // packed bf16 split store; lane covers k = [4*lane, 4*lane+4)
    unsigned h0, l0, h1, l1;
    split_pair(acc.x, acc.y, h0, l0);
    split_pair(acc.z, acc.w, h1, l1);
    g_agg[(size_t)node * K4 + lane] = make_uint4(h0, h1, l0, l1);
    if (lane == 0) {
        g_rowsum[node] = vsum;
        g_deg[node] = 0;              // self-clean for next launch
    }
}

// ---------------------------------------------------------------------------
// Kernel 3: dual GEMM. A (full-K, bf16-split) staged once from packed aggx.
// GEMM0: t = aggx @ W_gc; then t += rowsum*b_gc, ReLU, re-split into the SAME
// smem A buffer. GEMM1: out = rownorm(t @ W2^T + b2). No global intermediate.
// ---------------------------------------------------------------------------
__global__ void __launch_bounds__(256, 2)
dual_kernel(const float* __restrict__ b_gc, const float* __restrict__ b2,
            float* __restrict__ out, int n) {
    extern __shared__ unsigned smu[];
    unsigned* Ah = smu;                      // [128][68] full-K
    unsigned* Al = smu + 128 * AFSTR;
    unsigned* Bh = smu + 2 * 128 * AFSTR;    // [128][36] per-chunk
    unsigned* Bl = Bh + 128 * ASTR;

    const int tid  = threadIdx.x;
    const int lane = tid & 31;
    const int wid  = tid >> 5;
    const int gid  = lane >> 2;
    const int tg   = lane & 3;
    const int wm   = wid >> 1;
    const int wn   = wid & 1;
    const int rb   = blockIdx.x * 128;

    if (blockIdx.x == 0 && tid == 0) g_ovf_cnt = 0;   // reset for next launch

    // ---- stage A full-K from packed aggx ----
    {
        int rl = tid >> 4;            // 0..15
        int q  = tid & 15;            // 0..15
#pragma unroll
        for (int i = 0; i < 8; i++) {
            int row  = rl + 16 * i;
            int grow = rb + row;
            uint4 u0 = make_uint4(0u, 0u, 0u, 0u), u1 = u0;
            if (grow < n) {
                u0 = g_agg[(size_t)grow * K4 + q];
                u1 = g_agg[(size_t)grow * K4 + q + 16];
            }
            int sa = row * AFSTR;
            *(uint2*)(Ah + sa + 2 * q)        = make_uint2(u0.x, u0.y);
            *(uint2*)(Al + sa + 2 * q)        = make_uint2(u0.z, u0.w);
            *(uint2*)(Ah + sa + 2 * (q + 16)) = make_uint2(u1.x, u1.y);
            *(uint2*)(Al + sa + 2 * (q + 16)) = make_uint2(u1.z, u1.w);
        }
    }

    float acc[2][8][4];

    // ================= GEMM0: aggx @ W_gc =================
#pragma unroll
    for (int mt = 0; mt < 2; mt++)
#pragma unroll
        for (int nt = 0; nt < 8; nt++)
#pragma unroll
            for (int j = 0; j < 4; j++) acc[mt][nt][j] = 0.f;

#pragma unroll
    for (int kc0 = 0; kc0 < DDIM; kc0 += KC) {
        {
            int nn   = tid >> 1;
            int half = tid & 1;
            int gb = nn * K2 + (kc0 >> 1) + half * 16;
            int sb = nn * ASTR + half * 16;
#pragma unroll
            for (int j = 0; j < 4; j++) {
                *(uint4*)(Bh + sb + 4 * j) = *(const uint4*)(gW0h + gb + 4 * j);
                *(uint4*)(Bl + sb + 4 * j) = *(const uint4*)(gW0l + gb + 4 * j);
            }
        }
        __syncthreads();
#pragma unroll
        for (int ks = 0; ks < 4; ks++) {
            int kb = ks * 8;
            int ka = (kc0 >> 1) + kb;
            unsigned ah[2][4], al[2][4];
#pragma unroll
            for (int mt = 0; mt < 2; mt++) {
                int base = (wm * 32 + mt * 16 + gid) * AFSTR + ka + tg;
                ah[mt][0] = Ah[base];
                ah[mt][1] = Ah[base + 8 * AFSTR];
                ah[mt][2] = Ah[base + 4];
                ah[mt][3] = Ah[base + 8 * AFSTR + 4];
                al[mt][0] = Al[base];
                al[mt][1] = Al[base + 8 * AFSTR];
                al[mt][2] = Al[base + 4];
                al[mt][3] = Al[base + 8 * AFSTR + 4];
            }
#pragma unroll
            for (int nt = 0; nt < 8; nt++) {
                int nb = (wn * 64 + nt * 8 + gid) * ASTR + kb + tg;
                unsigned bh0 = Bh[nb], bh1 = Bh[nb + 4];
                unsigned bl0 = Bl[nb], bl1 = Bl[nb + 4];
#pragma unroll
                for (int mt = 0; mt < 2; mt++) {
                    mma_bf16(acc[mt][nt], ah[mt], bh0, bh1);
                    mma_bf16(acc[mt][nt], ah[mt], bl0, bl1);
                    mma_bf16(acc[mt][nt], al[mt], bh0, bh1);
                }
            }
        }
        __syncthreads();
    }

    // ---- mid: t = relu(acc + rowsum*b_gc), re-split into Ah/Al ----
#pragma unroll
    for (int mt = 0; mt < 2; mt++)
#pragma unroll
        for (int h = 0; h < 2; h++) {
            int row  = wm * 32 + mt * 16 + h * 8 + gid;
            int grow = rb + row;
            float rs = (grow < n) ? __ldg(g_rowsum + grow) : 0.f;
#pragma unroll
            for (int nt = 0; nt < 8; nt++) {
                int col = wn * 64 + nt * 8 + tg * 2;
                float bg0 = __ldg(b_gc + col), bg1 = __ldg(b_gc + col + 1);
                float v0 = fmaxf(fmaf(rs, bg0, acc[mt][nt][2 * h]), 0.f);
                float v1 = fmaxf(fmaf(rs, bg1, acc[mt][nt][2 * h + 1]), 0.f);
                unsigned hp, lp;
                split_pair(v0, v1, hp, lp);
                int k2 = wn * 32 + nt * 4 + tg;
                Ah[row * AFSTR + k2] = hp;
                Al[row * AFSTR + k2] = lp;
            }
        }

    // ================= GEMM1: t @ W2^T =================
#pragma unroll
    for (int mt = 0; mt < 2; mt++)
#pragma unroll
        for (int nt = 0; nt < 8; nt++)
#pragma unroll
            for (int j = 0; j < 4; j++) acc[mt][nt][j] = 0.f;

#pragma unroll
    for (int kc0 = 0; kc0 < DDIM; kc0 += KC) {
        {
            int nn   = tid >> 1;
            int half = tid & 1;
            int gb = nn * K2 + (kc0 >> 1) + half * 16;
            int sb = nn * ASTR + half * 16;
#pragma unroll
            for (int j = 0; j < 4; j++) {
                *(uint4*)(Bh + sb + 4 * j) = *(const uint4*)(gW1h + gb + 4 * j);
                *(uint4*)(Bl + sb + 4 * j) = *(const uint4*)(gW1l + gb + 4 * j);
            }
        }
        __syncthreads();     // covers A re-split writes (first iter) + B stage
#pragma unroll
        for (int ks = 0; ks < 4; ks++) {
            int kb = ks * 8;
            int ka = (kc0 >> 1) + kb;
            unsigned ah[2][4], al[2][4];
#pragma unroll
            for (int mt = 0; mt < 2; mt++) {
                int base = (wm * 32 + mt * 16 + gid) * AFSTR + ka + tg;
                ah[mt][0] = Ah[base];
                ah[mt][1] = Ah[base + 8 * AFSTR];
                ah[mt][2] = Ah[base + 4];
                ah[mt][3] = Ah[base + 8 * AFSTR + 4];
                al[mt][0] = Al[base];
                al[mt][1] = Al[base + 8 * AFSTR];
                al[mt][2] = Al[base + 4];
                al[mt][3] = Al[base + 8 * AFSTR + 4];
            }
#pragma unroll
            for (int nt = 0; nt < 8; nt++) {
                int nb = (wn * 64 + nt * 8 + gid) * ASTR + kb + tg;
                unsigned bh0 = Bh[nb], bh1 = Bh[nb + 4];
                unsigned bl0 = Bl[nb], bl1 = Bl[nb + 4];
#pragma unroll
                for (int mt = 0; mt < 2; mt++) {
                    mma_bf16(acc[mt][nt], ah[mt], bh0, bh1);
                    mma_bf16(acc[mt][nt], ah[mt], bl0, bl1);
                    mma_bf16(acc[mt][nt], al[mt], bh0, bh1);
                }
            }
        }
        __syncthreads();
    }

    // ---- epilogue: bias b2 + rownorm ----
    float* red = (float*)Bh;     // safe: sync above, Bh no longer read
#pragma unroll
    for (int mt = 0; mt < 2; mt++)
#pragma unroll
        for (int nt = 0; nt < 8; nt++) {
            int col = wn * 64 + nt * 8 + tg * 2;
            float b0 = __ldg(b2 + col), b1 = __ldg(b2 + col + 1);
            acc[mt][nt][0] += b0; acc[mt][nt][1] += b1;
            acc[mt][nt][2] += b0; acc[mt][nt][3] += b1;
        }
#pragma unroll
    for (int mt = 0; mt < 2; mt++)
#pragma unroll
        for (int h = 0; h < 2; h++) {
            float ss = 0.f;
#pragma unroll
            for (int nt = 0; nt < 8; nt++) {
                ss = fmaf(acc[mt][nt][2 * h], acc[mt][nt][2 * h], ss);
                ss = fmaf(acc[mt][nt][2 * h + 1], acc[mt][nt][2 * h + 1], ss);
            }
            ss += __shfl_xor_sync(0xffffffffu, ss, 1);
            ss += __shfl_xor_sync(0xffffffffu, ss, 2);
            if (tg == 0)
                red[(wm * 32 + mt * 16 + h * 8 + gid) * 2 + wn] = ss;
        }
    __syncthreads();
#pragma unroll
    for (int mt = 0; mt < 2; mt++)
#pragma unroll
        for (int h = 0; h < 2; h++) {
            int rl  = wm * 32 + mt * 16 + h * 8 + gid;
            int row = rb + rl;
            float inv = 1.f / sqrtf(red[rl * 2] + red[rl * 2 + 1]);
            if (row < n) {
#pragma unroll
                for (int nt = 0; nt < 8; nt++) {
                    int col = wn * 64 + nt * 8 + tg * 2;
                    float2 v = make_float2(acc[mt][nt][2 * h] * inv,
                                           acc[mt][nt][2 * h + 1] * inv);
                    *(float2*)(out + (size_t)row * DDIM + col) = v;
                }
            }
        }
}

// ---------------------------------------------------------------------------
extern "C" void kernel_launch(void* const* d_in, const int* in_sizes, int n_in,
                              void* d_out, int out_size) {
    const float* x    = (const float*)d_in[0];
    const float* vals = (const float*)d_in[1];
    const float* W_gc = (const float*)d_in[2];
    const float* b_gc = (const float*)d_in[3];
    const float* W2   = (const float*)d_in[4];
    const float* b2   = (const float*)d_in[5];
    const int*   src  = (const int*)d_in[6];
    const int*   dst  = (const int*)d_in[7];

    const int n = in_sizes[0] / DDIM;
    const int e = in_sizes[1];

    const int smem3 = (2 * 128 * AFSTR + 2 * 128 * ASTR) * 4;   // 106496 B
    cudaFuncSetAttribute(dual_kernel,
                         cudaFuncAttributeMaxDynamicSharedMemorySize, smem3);

    // 1) fill ELL || pre-split weights
    int fillchunks = (e + 1023) / 1024;
    int wblocks = (2 * DDIM * K2 + 255) / 256;     // 128
    fillw_kernel<<<fillchunks + wblocks, 256>>>(src, dst, vals, W_gc, W2,
                                                e, fillchunks);

    // 2) gather on x -> packed aggx + rowsum (self-cleans deg)
    long long gthreads = (long long)n * 32;
    gather_kernel<<<(int)((gthreads + 255) / 256), 256>>>(x, n);

    // 3) dual GEMM: out = rownorm(relu(aggx@W_gc + rowsum*b_gc) @ W2^T + b2)
    int gblocks = (n + 127) / 128;
    dual_kernel<<<gblocks, 256, smem3>>>(b_gc, b2, (float*)d_out, n);
}

// round 14
// speedup vs baseline: 1.0014x; 1.0014x over previous
#include <cuda_runtime.h>
#include <cuda_bf16.h>
#include <math.h>

#define DDIM 128
#define NMAX 50000
#define EMAX 800000
#define ASTR 36            // per-chunk bf16x2 stride (32 data + 4 pad), %32==4 -> conflict-free
#define AFSTR 68           // full-K bf16x2 stride (64 data + 4 pad), %32==4 -> conflict-free
#define KC   64            // k-chunk (32 bf16x2)
#define CAP  64            // ELL capacity per node (Poisson(16): max deg ~45)
#define OVFMAX 65536
#define K2   (DDIM / 2)    // 64 bf16x2 per row
#define K4   (DDIM / 4)    // 32 uint4 per packed row

// Scratch (alloc-free rule: __device__ globals; zero-initialized at load).
// State protocol across launches: g_deg self-cleaned by gather, g_ovf_cnt
// reset by dual_kernel, everything else fully rewritten each launch.
__device__ uint4    g_agg[(size_t)NMAX * K4];    // packed bf16-split aggx {h0,h1,l0,l1}
__device__ float    g_rowsum[NMAX];              // sum of vals per dst node
__device__ int      g_deg[NMAX];
__device__ uint2    g_ell[(size_t)NMAX * CAP];   // (src, val_bits) per slot
__device__ int      g_ovf_cnt;
__device__ uint4    g_ovf[OVFMAX];               // (src, dst, val_bits, -)
// pre-split weights, bf16x2 hi/lo, layout [n][k2]
__device__ unsigned gW0h[DDIM * K2], gW0l[DDIM * K2];
__device__ unsigned gW1h[DDIM * K2], gW1l[DDIM * K2];

// ---------------------------------------------------------------------------
__device__ __forceinline__ void split_pair(float x, float y, unsigned& hp, unsigned& lp) {
    __nv_bfloat16 hx = __float2bfloat16_rn(x);
    __nv_bfloat16 hy = __float2bfloat16_rn(y);
    __nv_bfloat16 lx = __float2bfloat16_rn(x - __bfloat162float(hx));
    __nv_bfloat16 ly = __float2bfloat16_rn(y - __bfloat162float(hy));
    hp = (unsigned)__bfloat16_as_ushort(hx) | ((unsigned)__bfloat16_as_ushort(hy) << 16);
    lp = (unsigned)__bfloat16_as_ushort(lx) | ((unsigned)__bfloat16_as_ushort(ly) << 16);
}

__device__ __forceinline__ void mma_bf16(float c[4], const unsigned a[4],
                                         unsigned b0, unsigned b1) {
    asm volatile(
        "mma.sync.aligned.m16n8k16.row.col.f32.bf16.bf16.f32 "
        "{%0,%1,%2,%3}, {%4,%5,%6,%7}, {%8,%9}, {%0,%1,%2,%3};"
        : "+f"(c[0]), "+f"(c[1]), "+f"(c[2]), "+f"(c[3])
        : "r"(a[0]), "r"(a[1]), "r"(a[2]), "r"(a[3]), "r"(b0), "r"(b1));
}

__device__ __forceinline__ void fma4(float4& a, float4 s, float v) {
    a.x = fmaf(s.x, v, a.x); a.y = fmaf(s.y, v, a.y);
    a.z = fmaf(s.z, v, a.z); a.w = fmaf(s.w, v, a.w);
}

// ---------------------------------------------------------------------------
// Kernel 1: ELL fill (ONE edge per thread - one atomic chain each, latency
// hidden by 25K warps) || weight pre-split, one grid.
// ---------------------------------------------------------------------------
__global__ void fillw_kernel(const int* __restrict__ src,
                             const int* __restrict__ dst,
                             const float* __restrict__ vals,
                             const float* __restrict__ W_gc,
                             const float* __restrict__ W2,
                             int e, int fillblocks) {
    int b = blockIdx.x;
    if (b < fillblocks) {
        int i = b * 256 + threadIdx.x;
        if (i >= e) return;
        int d = __ldg(dst + i);
        int s = __ldg(src + i);
        float v = __ldg(vals + i);
        int slot = atomicAdd(&g_deg[d], 1);
        if (slot < CAP) {
            g_ell[(size_t)d * CAP + slot] = make_uint2((unsigned)s, __float_as_uint(v));
        } else {
            int o = atomicAdd(&g_ovf_cnt, 1);
            if (o < OVFMAX)
                g_ovf[o] = make_uint4((unsigned)s, (unsigned)d, __float_as_uint(v), 0u);
        }
        return;
    }
    int i = (b - fillblocks) * 256 + threadIdx.x;      // [0, 32768)
    if (i < DDIM * K2) {                               // W_gc: [k][n] -> [n][k2]
        int nn = i & (DDIM - 1), k2 = i >> 7;
        float w0 = __ldg(W_gc + (size_t)(2 * k2) * DDIM + nn);
        float w1 = __ldg(W_gc + (size_t)(2 * k2 + 1) * DDIM + nn);
        unsigned hp, lp;
        split_pair(w0, w1, hp, lp);
        gW0h[nn * K2 + k2] = hp;
        gW0l[nn * K2 + k2] = lp;
    } else if (i < 2 * DDIM * K2) {                    // W2: [n][k] -> [n][k2]
        int j = i - DDIM * K2;
        int nn = j >> 6, k2 = j & 63;
        float w0 = __ldg(W2 + (size_t)nn * DDIM + 2 * k2);
        float w1 = __ldg(W2 + (size_t)nn * DDIM + 2 * k2 + 1);
        unsigned hp, lp;
        split_pair(w0, w1, hp, lp);
        gW1h[nn * K2 + k2] = hp;
        gW1l[nn * K2 + k2] = lp;
    }
}

// ---------------------------------------------------------------------------
// Kernel 2: gather on x (associativity: aggx = Adj @ x, rowsum = Adj @ 1).
// One warp per node, 8 edges in flight. Emits packed bf16-split aggx.
// Self-cleans g_deg for next launch.
// ---------------------------------------------------------------------------
__global__ void __launch_bounds__(256)
gather_kernel(const float* __restrict__ x, int n) {
    int g = blockIdx.x * blockDim.x + threadIdx.x;
    int node = g >> 5;
    int lane = g & 31;
    if (node >= n) return;

    int raw = __ldg(&g_deg[node]);
    int cnt = min(raw, CAP);
    const uint4* el4 = (const uint4*)(g_ell + (size_t)node * CAP);

    float4 acc = make_float4(0.f, 0.f, 0.f, 0.f);
    float vsum = 0.f;
    int nb8 = cnt >> 3;

    for (int q = 0; q < nb8; q++) {
        const uint4* p = el4 + 4 * q;
        uint4 m0 = __ldg(p),     m1 = __ldg(p + 1);
        uint4 m2 = __ldg(p + 2), m3 = __ldg(p + 3);
        float4 s0 = ((const float4*)(x + (size_t)m0.x * DDIM))[lane];
        float4 s1 = ((const float4*)(x + (size_t)m0.z * DDIM))[lane];
        float4 s2 = ((const float4*)(x + (size_t)m1.x * DDIM))[lane];
        float4 s3 = ((const float4*)(x + (size_t)m1.z * DDIM))[lane];
        float4 s4 = ((const float4*)(x + (size_t)m2.x * DDIM))[lane];
        float4 s5 = ((const float4*)(x + (size_t)m2.z * DDIM))[lane];
        float4 s6 = ((const float4*)(x + (size_t)m3.x * DDIM))[lane];
        float4 s7 = ((const float4*)(x + (size_t)m3.z * DDIM))[lane];
        float v0 = __uint_as_float(m0.y), v1 = __uint_as_float(m0.w);
        float v2 = __uint_as_float(m1.y), v3 = __uint_as_float(m1.w);
        float v4 = __uint_as_float(m2.y), v5 = __uint_as_float(m2.w);
        float v6 = __uint_as_float(m3.y), v7 = __uint_as_float(m3.w);
        fma4(acc, s0, v0); fma4(acc, s1, v1);
        fma4(acc, s2, v2); fma4(acc, s3, v3);
        fma4(acc, s4, v4); fma4(acc, s5, v5);
        fma4(acc, s6, v6); fma4(acc, s7, v7);
        vsum += v0 + v1 + v2 + v3 + v4 + v5 + v6 + v7;
    }
    int i = nb8 * 8;
    if (i + 3 < cnt) {
        const uint4* p = el4 + (i >> 1);
        uint4 m0 = __ldg(p), m1 = __ldg(p + 1);
        float4 s0 = ((const float4*)(x + (size_t)m0.x * DDIM))[lane];
        float4 s1 = ((const float4*)(x + (size_t)m0.z * DDIM))[lane];
        float4 s2 = ((const float4*)(x + (size_t)m1.x * DDIM))[lane];
        float4 s3 = ((const float4*)(x + (size_t)m1.z * DDIM))[lane];
        float v0 = __uint_as_float(m0.y), v1 = __uint_as_float(m0.w);
        float v2 = __uint_as_float(m1.y), v3 = __uint_as_float(m1.w);
        fma4(acc, s0, v0); fma4(acc, s1, v1);
        fma4(acc, s2, v2); fma4(acc, s3, v3);
        vsum += v0 + v1 + v2 + v3;
        i += 4;
    }
    for (; i < cnt; i++) {
        uint2 m = __ldg(g_ell + (size_t)node * CAP + i);
        float v = __uint_as_float(m.y);
        float4 s = ((const float4*)(x + (size_t)m.x * DDIM))[lane];
        fma4(acc, s, v);
        vsum += v;
    }
    if (raw > CAP) {        // ~never: this node's overflow edges
        int c = min(g_ovf_cnt, OVFMAX);
        for (int j = 0; j < c; j++) {
            uint4 m = g_ovf[j];
            if (m.y == (unsigned)node) {
                float v = __uint_as_float(m.z);
                float4 s = ((const float4*)(x + (size_t)m.x * DDIM))[lane];
                fma4(acc, s, v);
                vsum += v;
            }
        }
    }

    // packed bf16 split store; lane covers k = [4*lane, 4*lane+4)
    unsigned h0, l0, h1, l1;
    split_pair(acc.x, acc.y, h0, l0);
    split_pair(acc.z, acc.w, h1, l1);
    g_agg[(size_t)node * K4 + lane] = make_uint4(h0, h1, l0, l1);
    if (lane == 0) {
        g_rowsum[node] = vsum;
        g_deg[node] = 0;              // self-clean for next launch
    }
}

// ---------------------------------------------------------------------------
// Kernel 3: dual GEMM. A (full-K, bf16-split) staged once from packed aggx.
// GEMM0: t = aggx @ W_gc; then t += rowsum*b_gc, ReLU, re-split into the SAME
// smem A buffer. GEMM1: out = rownorm(t @ W2^T + b2). No global intermediate.
// ---------------------------------------------------------------------------
__global__ void __launch_bounds__(256, 2)
dual_kernel(const float* __restrict__ b_gc, const float* __restrict__ b2,
            float* __restrict__ out, int n) {
    extern __shared__ unsigned smu[];
    unsigned* Ah = smu;                      // [128][68] full-K
    unsigned* Al = smu + 128 * AFSTR;
    unsigned* Bh = smu + 2 * 128 * AFSTR;    // [128][36] per-chunk
    unsigned* Bl = Bh + 128 * ASTR;

    const int tid  = threadIdx.x;
    const int lane = tid & 31;
    const int wid  = tid >> 5;
    const int gid  = lane >> 2;
    const int tg   = lane & 3;
    const int wm   = wid >> 1;
    const int wn   = wid & 1;
    const int rb   = blockIdx.x * 128;

    if (blockIdx.x == 0 && tid == 0) g_ovf_cnt = 0;   // reset for next launch

    // ---- stage A full-K from packed aggx ----
    {
        int rl = tid >> 4;            // 0..15
        int q  = tid & 15;            // 0..15
#pragma unroll
        for (int i = 0; i < 8; i++) {
            int row  = rl + 16 * i;
            int grow = rb + row;
            uint4 u0 = make_uint4(0u, 0u, 0u, 0u), u1 = u0;
            if (grow < n) {
                u0 = g_agg[(size_t)grow * K4 + q];
                u1 = g_agg[(size_t)grow * K4 + q + 16];
            }
            int sa = row * AFSTR;
            *(uint2*)(Ah + sa + 2 * q)        = make_uint2(u0.x, u0.y);
            *(uint2*)(Al + sa + 2 * q)        = make_uint2(u0.z, u0.w);
            *(uint2*)(Ah + sa + 2 * (q + 16)) = make_uint2(u1.x, u1.y);
            *(uint2*)(Al + sa + 2 * (q + 16)) = make_uint2(u1.z, u1.w);
        }
    }

    float acc[2][8][4];

    // ================= GEMM0: aggx @ W_gc =================
#pragma unroll
    for (int mt = 0; mt < 2; mt++)
#pragma unroll
        for (int nt = 0; nt < 8; nt++)
#pragma unroll
            for (int j = 0; j < 4; j++) acc[mt][nt][j] = 0.f;

#pragma unroll
    for (int kc0 = 0; kc0 < DDIM; kc0 += KC) {
        {
            int nn   = tid >> 1;
            int half = tid & 1;
            int gb = nn * K2 + (kc0 >> 1) + half * 16;
            int sb = nn * ASTR + half * 16;
#pragma unroll
            for (int j = 0; j < 4; j++) {
                *(uint4*)(Bh + sb + 4 * j) = *(const uint4*)(gW0h + gb + 4 * j);
                *(uint4*)(Bl + sb + 4 * j) = *(const uint4*)(gW0l + gb + 4 * j);
            }
        }
        __syncthreads();
#pragma unroll
        for (int ks = 0; ks < 4; ks++) {
            int kb = ks * 8;
            int ka = (kc0 >> 1) + kb;
            unsigned ah[2][4], al[2][4];
#pragma unroll
            for (int mt = 0; mt < 2; mt++) {
                int base = (wm * 32 + mt * 16 + gid) * AFSTR + ka + tg;
                ah[mt][0] = Ah[base];
                ah[mt][1] = Ah[base + 8 * AFSTR];
                ah[mt][2] = Ah[base + 4];
                ah[mt][3] = Ah[base + 8 * AFSTR + 4];
                al[mt][0] = Al[base];
                al[mt][1] = Al[base + 8 * AFSTR];
                al[mt][2] = Al[base + 4];
                al[mt][3] = Al[base + 8 * AFSTR + 4];
            }
#pragma unroll
            for (int nt = 0; nt < 8; nt++) {
                int nb = (wn * 64 + nt * 8 + gid) * ASTR + kb + tg;
                unsigned bh0 = Bh[nb], bh1 = Bh[nb + 4];
                unsigned bl0 = Bl[nb], bl1 = Bl[nb + 4];
#pragma unroll
                for (int mt = 0; mt < 2; mt++) {
                    mma_bf16(acc[mt][nt], ah[mt], bh0, bh1);
                    mma_bf16(acc[mt][nt], ah[mt], bl0, bl1);
                    mma_bf16(acc[mt][nt], al[mt], bh0, bh1);
                }
            }
        }
        __syncthreads();
    }

    // ---- mid: t = relu(acc + rowsum*b_gc), re-split into Ah/Al ----
#pragma unroll
    for (int mt = 0; mt < 2; mt++)
#pragma unroll
        for (int h = 0; h < 2; h++) {
            int row  = wm * 32 + mt * 16 + h * 8 + gid;
            int grow = rb + row;
            float rs = (grow < n) ? __ldg(g_rowsum + grow) : 0.f;
#pragma unroll
            for (int nt = 0; nt < 8; nt++) {
                int col = wn * 64 + nt * 8 + tg * 2;
                float bg0 = __ldg(b_gc + col), bg1 = __ldg(b_gc + col + 1);
                float v0 = fmaxf(fmaf(rs, bg0, acc[mt][nt][2 * h]), 0.f);
                float v1 = fmaxf(fmaf(rs, bg1, acc[mt][nt][2 * h + 1]), 0.f);
                unsigned hp, lp;
                split_pair(v0, v1, hp, lp);
                int k2 = wn * 32 + nt * 4 + tg;
                Ah[row * AFSTR + k2] = hp;
                Al[row * AFSTR + k2] = lp;
            }
        }

    // ================= GEMM1: t @ W2^T =================
#pragma unroll
    for (int mt = 0; mt < 2; mt++)
#pragma unroll
        for (int nt = 0; nt < 8; nt++)
#pragma unroll
            for (int j = 0; j < 4; j++) acc[mt][nt][j] = 0.f;

#pragma unroll
    for (int kc0 = 0; kc0 < DDIM; kc0 += KC) {
        {
            int nn   = tid >> 1;
            int half = tid & 1;
            int gb = nn * K2 + (kc0 >> 1) + half * 16;
            int sb = nn * ASTR + half * 16;
#pragma unroll
            for (int j = 0; j < 4; j++) {
                *(uint4*)(Bh + sb + 4 * j) = *(const uint4*)(gW1h + gb + 4 * j);
                *(uint4*)(Bl + sb + 4 * j) = *(const uint4*)(gW1l + gb + 4 * j);
            }
        }
        __syncthreads();     // covers A re-split writes (first iter) + B stage
#pragma unroll
        for (int ks = 0; ks < 4; ks++) {
            int kb = ks * 8;
            int ka = (kc0 >> 1) + kb;
            unsigned ah[2][4], al[2][4];
#pragma unroll
            for (int mt = 0; mt < 2; mt++) {
                int base = (wm * 32 + mt * 16 + gid) * AFSTR + ka + tg;
                ah[mt][0] = Ah[base];
                ah[mt][1] = Ah[base + 8 * AFSTR];
                ah[mt][2] = Ah[base + 4];
                ah[mt][3] = Ah[base + 8 * AFSTR + 4];
                al[mt][0] = Al[base];
                al[mt][1] = Al[base + 8 * AFSTR];
                al[mt][2] = Al[base + 4];
                al[mt][3] = Al[base + 8 * AFSTR + 4];
            }
#pragma unroll
            for (int nt = 0; nt < 8; nt++) {
                int nb = (wn * 64 + nt * 8 + gid) * ASTR + kb + tg;
                unsigned bh0 = Bh[nb], bh1 = Bh[nb + 4];
                unsigned bl0 = Bl[nb], bl1 = Bl[nb + 4];
#pragma unroll
                for (int mt = 0; mt < 2; mt++) {
                    mma_bf16(acc[mt][nt], ah[mt], bh0, bh1);
                    mma_bf16(acc[mt][nt], ah[mt], bl0, bl1);
                    mma_bf16(acc[mt][nt], al[mt], bh0, bh1);
                }
            }
        }
        __syncthreads();
    }

    // ---- epilogue: bias b2 + rownorm ----
    float* red = (float*)Bh;     // safe: sync above, Bh no longer read
#pragma unroll
    for (int mt = 0; mt < 2; mt++)
#pragma unroll
        for (int nt = 0; nt < 8; nt++) {
            int col = wn * 64 + nt * 8 + tg * 2;
            float b0 = __ldg(b2 + col), b1 = __ldg(b2 + col + 1);
            acc[mt][nt][0] += b0; acc[mt][nt][1] += b1;
            acc[mt][nt][2] += b0; acc[mt][nt][3] += b1;
        }
#pragma unroll
    for (int mt = 0; mt < 2; mt++)
#pragma unroll
        for (int h = 0; h < 2; h++) {
            float ss = 0.f;
#pragma unroll
            for (int nt = 0; nt < 8; nt++) {
                ss = fmaf(acc[mt][nt][2 * h], acc[mt][nt][2 * h], ss);
                ss = fmaf(acc[mt][nt][2 * h + 1], acc[mt][nt][2 * h + 1], ss);
            }
            ss += __shfl_xor_sync(0xffffffffu, ss, 1);
            ss += __shfl_xor_sync(0xffffffffu, ss, 2);
            if (tg == 0)
                red[(wm * 32 + mt * 16 + h * 8 + gid) * 2 + wn] = ss;
        }
    __syncthreads();
#pragma unroll
    for (int mt = 0; mt < 2; mt++)
#pragma unroll
        for (int h = 0; h < 2; h++) {
            int rl  = wm * 32 + mt * 16 + h * 8 + gid;
            int row = rb + rl;
            float inv = 1.f / sqrtf(red[rl * 2] + red[rl * 2 + 1]);
            if (row < n) {
#pragma unroll
                for (int nt = 0; nt < 8; nt++) {
                    int col = wn * 64 + nt * 8 + tg * 2;
                    float2 v = make_float2(acc[mt][nt][2 * h] * inv,
                                           acc[mt][nt][2 * h + 1] * inv);
                    *(float2*)(out + (size_t)row * DDIM + col) = v;
                }
            }
        }
}

// ---------------------------------------------------------------------------
extern "C" void kernel_launch(void* const* d_in, const int* in_sizes, int n_in,
                              void* d_out, int out_size) {
    const float* x    = (const float*)d_in[0];
    const float* vals = (const float*)d_in[1];
    const float* W_gc = (const float*)d_in[2];
    const float* b_gc = (const float*)d_in[3];
    const float* W2   = (const float*)d_in[4];
    const float* b2   = (const float*)d_in[5];
    const int*   src  = (const int*)d_in[6];
    const int*   dst  = (const int*)d_in[7];

    const int n = in_sizes[0] / DDIM;
    const int e = in_sizes[1];

    const int smem3 = (2 * 128 * AFSTR + 2 * 128 * ASTR) * 4;   // 106496 B
    cudaFuncSetAttribute(dual_kernel,
                         cudaFuncAttributeMaxDynamicSharedMemorySize, smem3);

    // 1) fill ELL (1 edge/thread) || pre-split weights
    int fillblocks = (e + 255) / 256;
    int wblocks = (2 * DDIM * K2 + 255) / 256;     // 128
    fillw_kernel<<<fillblocks + wblocks, 256>>>(src, dst, vals, W_gc, W2,
                                                e, fillblocks);

    // 2) gather on x -> packed aggx + rowsum (self-cleans deg)
    long long gthreads = (long long)n * 32;
    gather_kernel<<<(int)((gthreads + 255) / 256), 256>>>(x, n);

    // 3) dual GEMM: out = rownorm(relu(aggx@W_gc + rowsum*b_gc) @ W2^T + b2)
    int gblocks = (n + 127) / 128;
    dual_kernel<<<gblocks, 256, smem3>>>(b_gc, b2, (float*)d_out, n);
}